// round 8
// baseline (speedup 1.0000x reference)
#include <cuda_runtime.h>
#include <cuda_bf16.h>
#include <cstdint>

// Problem dims
#define BB 8
#define SS 1024          // IMG*IMG
#define EE 768           // D_EMBED == D_MODEL
#define NH 12
#define DD 64

// ---------------- scratch (device globals; no allocs allowed) ----------------
__device__ float g_q[BB * SS * EE];
__device__ float g_k[BB * SS * EE];
__device__ float g_v[BB * SS * EE];
__device__ float g_ctx[BB * SS * EE];
// per-row partial sums of exp(scores): [bh*SS + row][32 n-tiles]
__device__ float g_partials[(size_t)BB * NH * SS * 32];

// =============================================================================
// bf16 split helpers: x = hi + lo, both bf16. Packed pairs along k.
// =============================================================================
__device__ __forceinline__ void split2_bf16(float x0, float x1,
                                            uint32_t& hw, uint32_t& lw) {
    __nv_bfloat162 h = __floats2bfloat162_rn(x0, x1);
    float2 hf = __bfloat1622float2(h);
    __nv_bfloat162 l = __floats2bfloat162_rn(x0 - hf.x, x1 - hf.y);
    hw = *reinterpret_cast<uint32_t*>(&h);
    lw = *reinterpret_cast<uint32_t*>(&l);
}

__device__ __forceinline__ void mma_bf16(float* d, const uint32_t* a, const uint32_t* b) {
    asm volatile(
        "mma.sync.aligned.m16n8k16.row.col.f32.bf16.bf16.f32 "
        "{%0,%1,%2,%3}, {%4,%5,%6,%7}, {%8,%9}, {%0,%1,%2,%3};"
        : "+f"(d[0]), "+f"(d[1]), "+f"(d[2]), "+f"(d[3])
        : "r"(a[0]), "r"(a[1]), "r"(a[2]), "r"(a[3]),
          "r"(b[0]), "r"(b[1]));
}

#define MMA3(accp, ah_, al_, bh_, bl_) \
    do { mma_bf16(accp, ah_, bh_); mma_bf16(accp, ah_, bl_); mma_bf16(accp, al_, bh_); } while (0)

// =============================================================================
// Kernel 1: QKV projection, split-bf16 mma (round 7, unchanged).
// =============================================================================
#define GP_AP 136
#define GP_BP 20
#define GP_AHo 0
#define GP_ALo 2176
#define GP_BHo 4352
#define GP_BLo 5632
#define GP_SMEM_WORDS 6912
#define GP_SMEM_BYTES (GP_SMEM_WORDS * 4)

__global__ __launch_bounds__(256) void proj_mma_kernel(
    const float* __restrict__ xq, const float* __restrict__ xk, const float* __restrict__ xv,
    const float* __restrict__ wq, const float* __restrict__ wk, const float* __restrict__ wv,
    const float* __restrict__ bq, const float* __restrict__ bk, const float* __restrict__ bv)
{
    extern __shared__ uint32_t su[];
    uint32_t* AH = su + GP_AHo;
    uint32_t* AL = su + GP_ALo;
    uint32_t* BH = su + GP_BHo;
    uint32_t* BL = su + GP_BLo;

    const int mat = blockIdx.z >> 3;
    const int b   = blockIdx.z & 7;

    const float* x; const float* w; const float* bi; float* y;
    if (mat == 0)      { x = xq; w = wq; bi = bq; y = g_q; }
    else if (mat == 1) { x = xk; w = wk; bi = bk; y = g_k; }
    else               { x = xv; w = wv; bi = bv; y = g_v; }
    x += (size_t)b * EE * SS;
    y += (size_t)b * SS * EE;

    const int m0 = blockIdx.x * 128;
    const int n0 = blockIdx.y * 64;

    const int tid  = threadIdx.x;
    const int lane = tid & 31;
    const int w8   = tid >> 5;
    const int wm   = w8 >> 1;
    const int wn   = w8 & 1;
    const int gid  = lane >> 2;
    const int ctid = lane & 3;

    float acc[2][4][4];
    #pragma unroll
    for (int i = 0; i < 2; i++)
        #pragma unroll
        for (int j = 0; j < 4; j++)
            #pragma unroll
            for (int q = 0; q < 4; q++) acc[i][j][q] = 0.f;

    for (int kg = 0; kg < EE; kg += 32) {
        __syncthreads();
        #pragma unroll
        for (int p = 0; p < 2; p++) {
            int idx = tid + p * 256;
            int j   = idx >> 5;
            int m4  = (idx & 31) << 2;
            const float* xr = x + (size_t)(kg + 2 * j) * SS + m0 + m4;
            float4 ra = *(const float4*)xr;
            float4 rb = *(const float4*)(xr + SS);
            uint4 hv, lv;
            split2_bf16(ra.x, rb.x, hv.x, lv.x);
            split2_bf16(ra.y, rb.y, hv.y, lv.y);
            split2_bf16(ra.z, rb.z, hv.z, lv.z);
            split2_bf16(ra.w, rb.w, hv.w, lv.w);
            *(uint4*)(AH + j * GP_AP + m4) = hv;
            *(uint4*)(AL + j * GP_AP + m4) = lv;
        }
        {
            int r  = tid >> 2;
            int kq = (tid & 3) << 3;
            const float* wr = w + (size_t)(n0 + r) * EE + kg + kq;
            float4 b0 = *(const float4*)wr;
            float4 b1 = *(const float4*)(wr + 4);
            uint4 hv, lv;
            split2_bf16(b0.x, b0.y, hv.x, lv.x);
            split2_bf16(b0.z, b0.w, hv.y, lv.y);
            split2_bf16(b1.x, b1.y, hv.z, lv.z);
            split2_bf16(b1.z, b1.w, hv.w, lv.w);
            *(uint4*)(BH + r * GP_BP + (tid & 3) * 4) = hv;
            *(uint4*)(BL + r * GP_BP + (tid & 3) * 4) = lv;
        }
        __syncthreads();

        #pragma unroll
        for (int kwb = 0; kwb < 16; kwb += 8) {
            uint32_t ah[2][4], al[2][4];
            #pragma unroll
            for (int mt = 0; mt < 2; mt++) {
                int mrow = wm * 32 + mt * 16 + gid;
                const uint32_t* ph = AH + (kwb + ctid) * GP_AP + mrow;
                const uint32_t* pl = AL + (kwb + ctid) * GP_AP + mrow;
                ah[mt][0] = ph[0];          ah[mt][1] = ph[8];
                ah[mt][2] = ph[4*GP_AP];    ah[mt][3] = ph[4*GP_AP + 8];
                al[mt][0] = pl[0];          al[mt][1] = pl[8];
                al[mt][2] = pl[4*GP_AP];    al[mt][3] = pl[4*GP_AP + 8];
            }
            #pragma unroll
            for (int nt = 0; nt < 4; nt++) {
                int nrow = wn * 32 + nt * 8 + gid;
                const uint32_t* pbh = BH + nrow * GP_BP + kwb + ctid;
                const uint32_t* pbl = BL + nrow * GP_BP + kwb + ctid;
                uint32_t bh_[2] = { pbh[0], pbh[4] };
                uint32_t bl_[2] = { pbl[0], pbl[4] };
                #pragma unroll
                for (int mt = 0; mt < 2; mt++)
                    MMA3(acc[mt][nt], ah[mt], al[mt], bh_, bl_);
            }
        }
    }

    #pragma unroll
    for (int nt = 0; nt < 4; nt++) {
        int col = n0 + wn * 32 + nt * 8 + 2 * ctid;
        float b0 = bi[col], b1 = bi[col + 1];
        #pragma unroll
        for (int mt = 0; mt < 2; mt++) {
            int row = m0 + wm * 32 + mt * 16 + gid;
            *(float2*)(y + (size_t)row * EE + col) =
                make_float2(acc[mt][nt][0] + b0, acc[mt][nt][1] + b1);
            *(float2*)(y + (size_t)(row + 8) * EE + col) =
                make_float2(acc[mt][nt][2] + b0, acc[mt][nt][3] + b1);
        }
    }
}

// =============================================================================
// Kernel 2a: scores GEMM + fused exp + per-row partial sums.
//   P~ = exp(Q.K^T / 8) (unnormalized) written to probs buffer.
//   Row partial sums (over this block's 2x32-col slabs) -> g_partials.
// No max subtraction: scores ~N(0,1), |s| <~ 6, exp is safe in fp32.
// =============================================================================
#define SK_P 36
#define SK_AHo 0
#define SK_ALo 4608
#define SK_BHo 9216
#define SK_BLo 11520
#define SK_SMEM_WORDS 13824
#define SK_SMEM_BYTES (SK_SMEM_WORDS * 4)

__global__ __launch_bounds__(256) void scores_mma_kernel(float* __restrict__ probs)
{
    extern __shared__ uint32_t su[];
    uint32_t* AH = su + SK_AHo;
    uint32_t* AL = su + SK_ALo;
    uint32_t* BH = su + SK_BHo;
    uint32_t* BL = su + SK_BLo;

    const int bh = blockIdx.z;
    const int b  = bh / NH;
    const int h  = bh % NH;
    const int m0 = blockIdx.x * 128;
    const int n0 = blockIdx.y * 64;

    const float* qp = g_q + ((size_t)b * SS) * EE + h * DD;
    const float* kp = g_k + ((size_t)b * SS) * EE + h * DD;

    const int tid  = threadIdx.x;
    const int lane = tid & 31;
    const int w8   = tid >> 5;
    const int wm   = w8 >> 1;
    const int wn   = w8 & 1;
    const int gid  = lane >> 2;
    const int ctid = lane & 3;

    #pragma unroll
    for (int p = 0; p < 4; p++) {
        int idx = tid + p * 256;
        int r   = idx >> 3;
        int kq  = (idx & 7) << 3;
        const float* qr = qp + (size_t)(m0 + r) * EE + kq;
        float4 a0 = *(const float4*)qr;
        float4 a1 = *(const float4*)(qr + 4);
        uint4 hv, lv;
        split2_bf16(a0.x, a0.y, hv.x, lv.x);
        split2_bf16(a0.z, a0.w, hv.y, lv.y);
        split2_bf16(a1.x, a1.y, hv.z, lv.z);
        split2_bf16(a1.z, a1.w, hv.w, lv.w);
        *(uint4*)(AH + r * SK_P + (idx & 7) * 4) = hv;
        *(uint4*)(AL + r * SK_P + (idx & 7) * 4) = lv;
    }
    #pragma unroll
    for (int p = 0; p < 2; p++) {
        int idx = tid + p * 256;
        int r   = idx >> 3;
        int kq  = (idx & 7) << 3;
        const float* kr = kp + (size_t)(n0 + r) * EE + kq;
        float4 b0 = *(const float4*)kr;
        float4 b1 = *(const float4*)(kr + 4);
        uint4 hv, lv;
        split2_bf16(b0.x, b0.y, hv.x, lv.x);
        split2_bf16(b0.z, b0.w, hv.y, lv.y);
        split2_bf16(b1.x, b1.y, hv.z, lv.z);
        split2_bf16(b1.z, b1.w, hv.w, lv.w);
        *(uint4*)(BH + r * SK_P + (idx & 7) * 4) = hv;
        *(uint4*)(BL + r * SK_P + (idx & 7) * 4) = lv;
    }
    __syncthreads();

    float acc[2][4][4];
    #pragma unroll
    for (int i = 0; i < 2; i++)
        #pragma unroll
        for (int j = 0; j < 4; j++)
            #pragma unroll
            for (int q = 0; q < 4; q++) acc[i][j][q] = 0.f;

    #pragma unroll
    for (int kwb = 0; kwb < 32; kwb += 8) {
        uint32_t ah[2][4], al[2][4];
        #pragma unroll
        for (int mt = 0; mt < 2; mt++) {
            int mrow = wm * 32 + mt * 16 + gid;
            const uint32_t* ph = AH + mrow * SK_P + kwb + ctid;
            const uint32_t* pl = AL + mrow * SK_P + kwb + ctid;
            ah[mt][0] = ph[0];          ah[mt][1] = ph[8*SK_P];
            ah[mt][2] = ph[4];          ah[mt][3] = ph[8*SK_P + 4];
            al[mt][0] = pl[0];          al[mt][1] = pl[8*SK_P];
            al[mt][2] = pl[4];          al[mt][3] = pl[8*SK_P + 4];
        }
        #pragma unroll
        for (int nt = 0; nt < 4; nt++) {
            int nrow = wn * 32 + nt * 8 + gid;
            const uint32_t* pbh = BH + nrow * SK_P + kwb + ctid;
            const uint32_t* pbl = BL + nrow * SK_P + kwb + ctid;
            uint32_t bh_[2] = { pbh[0], pbh[4] };
            uint32_t bl_[2] = { pbl[0], pbl[4] };
            #pragma unroll
            for (int mt = 0; mt < 2; mt++)
                MMA3(acc[mt][nt], ah[mt], al[mt], bh_, bl_);
        }
    }

    // ---- fused exp epilogue + per-row partial sums ----
    float* pbase = probs + (size_t)bh * SS * SS;
    float rs[2][2];   // [mt][row-half] partial sums over this warp's 32 cols
    rs[0][0] = rs[0][1] = rs[1][0] = rs[1][1] = 0.f;

    #pragma unroll
    for (int mt = 0; mt < 2; mt++)
        #pragma unroll
        for (int nt = 0; nt < 4; nt++) {
            float e0 = __expf(acc[mt][nt][0] * 0.125f);
            float e1 = __expf(acc[mt][nt][1] * 0.125f);
            float e2 = __expf(acc[mt][nt][2] * 0.125f);
            float e3 = __expf(acc[mt][nt][3] * 0.125f);
            int row = m0 + wm * 32 + mt * 16 + gid;
            int col = n0 + wn * 32 + nt * 8 + 2 * ctid;
            *(float2*)(pbase + (size_t)row * SS + col)       = make_float2(e0, e1);
            *(float2*)(pbase + (size_t)(row + 8) * SS + col) = make_float2(e2, e3);
            rs[mt][0] += e0 + e1;
            rs[mt][1] += e2 + e3;
        }

    // reduce over the 4 ctid lanes that share a row
    #pragma unroll
    for (int o = 1; o <= 2; o <<= 1) {
        rs[0][0] += __shfl_xor_sync(0xFFFFFFFFu, rs[0][0], o);
        rs[0][1] += __shfl_xor_sync(0xFFFFFFFFu, rs[0][1], o);
        rs[1][0] += __shfl_xor_sync(0xFFFFFFFFu, rs[1][0], o);
        rs[1][1] += __shfl_xor_sync(0xFFFFFFFFu, rs[1][1], o);
    }
    if (ctid == 0) {
        int nidx = blockIdx.y * 2 + wn;   // 0..31
        #pragma unroll
        for (int mt = 0; mt < 2; mt++) {
            int row = m0 + wm * 32 + mt * 16 + gid;
            g_partials[((size_t)bh * SS + row) * 32 + nidx]       = rs[mt][0];
            g_partials[((size_t)bh * SS + row + 8) * 32 + nidx]   = rs[mt][1];
        }
    }
}

// =============================================================================
// Kernel 2c: ctx GEMM with fused normalization.
//   Prologue: invs[row] = 1 / sum(g_partials[row][0..31]).
//   A-staging: load P~ chunk, scale by invs, WRITE normalized probs back,
//   feed normalized values to split-bf16 mma.
// =============================================================================
#define CX_AP 20
#define CX_BP 72
#define CX_AHo 0
#define CX_ALo 2560
#define CX_BHo 5120
#define CX_BLo 6272
#define CX_SMEM_WORDS 7424
#define CX_SMEM_BYTES (CX_SMEM_WORDS * 4)

__global__ __launch_bounds__(256) void ctx_mma_kernel(float* __restrict__ probs)
{
    extern __shared__ uint32_t su[];
    uint32_t* AH = su + CX_AHo;
    uint32_t* AL = su + CX_ALo;
    uint32_t* BH = su + CX_BHo;
    uint32_t* BL = su + CX_BLo;

    __shared__ float invs[128];

    const int bh = blockIdx.z;
    const int b  = bh / NH;
    const int h  = bh % NH;
    const int m0 = blockIdx.x * 128;

    float* pb = probs + (size_t)bh * SS * SS;
    const float* vb = g_v + ((size_t)b * SS) * EE + h * DD;

    const int tid  = threadIdx.x;
    const int lane = tid & 31;
    const int w8   = tid >> 5;
    const int wm   = w8 >> 1;
    const int wn   = w8 & 1;
    const int gid  = lane >> 2;
    const int ctid = lane & 3;

    // ---- prologue: row inverse sums ----
    if (tid < 128) {
        const float* pp = g_partials + ((size_t)bh * SS + m0 + tid) * 32;
        float s = 0.f;
        #pragma unroll
        for (int i = 0; i < 32; i++) s += pp[i];
        invs[tid] = 1.f / s;
    }
    __syncthreads();

    float acc[2][4][4];
    #pragma unroll
    for (int i = 0; i < 2; i++)
        #pragma unroll
        for (int j = 0; j < 4; j++)
            #pragma unroll
            for (int q = 0; q < 4; q++) acc[i][j][q] = 0.f;

    for (int kg = 0; kg < SS; kg += 32) {
        __syncthreads();
        // stage A (P~): 128 rows x 32 k; normalize, write back, pack bf16
        #pragma unroll
        for (int p = 0; p < 2; p++) {
            int idx = tid + p * 256;
            int r   = idx >> 2;
            int kq  = (idx & 3) << 3;
            float* pr = pb + (size_t)(m0 + r) * SS + kg + kq;
            float4 a0 = *(const float4*)pr;
            float4 a1 = *(const float4*)(pr + 4);
            float iv = invs[r];
            a0.x *= iv; a0.y *= iv; a0.z *= iv; a0.w *= iv;
            a1.x *= iv; a1.y *= iv; a1.z *= iv; a1.w *= iv;
            *(float4*)pr       = a0;   // normalized probs output
            *(float4*)(pr + 4) = a1;
            uint4 hv, lv;
            split2_bf16(a0.x, a0.y, hv.x, lv.x);
            split2_bf16(a0.z, a0.w, hv.y, lv.y);
            split2_bf16(a1.x, a1.y, hv.z, lv.z);
            split2_bf16(a1.z, a1.w, hv.w, lv.w);
            *(uint4*)(AH + r * CX_AP + (idx & 3) * 4) = hv;
            *(uint4*)(AL + r * CX_AP + (idx & 3) * 4) = lv;
        }
        // stage B (V): 32 k-rows x 64 d -> packed k-major Bt[kw][n]
        {
            int j  = tid >> 4;
            int d4 = (tid & 15) << 2;
            const float* vr = vb + (size_t)(kg + 2 * j) * EE + d4;
            float4 r0 = *(const float4*)vr;
            float4 r1 = *(const float4*)(vr + EE);
            uint4 hv, lv;
            split2_bf16(r0.x, r1.x, hv.x, lv.x);
            split2_bf16(r0.y, r1.y, hv.y, lv.y);
            split2_bf16(r0.z, r1.z, hv.z, lv.z);
            split2_bf16(r0.w, r1.w, hv.w, lv.w);
            *(uint4*)(BH + j * CX_BP + d4) = hv;
            *(uint4*)(BL + j * CX_BP + d4) = lv;
        }
        __syncthreads();

        #pragma unroll
        for (int kwb = 0; kwb < 16; kwb += 8) {
            uint32_t ah[2][4], al[2][4];
            #pragma unroll
            for (int mt = 0; mt < 2; mt++) {
                int mrow = wm * 32 + mt * 16 + gid;
                const uint32_t* ph = AH + mrow * CX_AP + kwb + ctid;
                const uint32_t* pl = AL + mrow * CX_AP + kwb + ctid;
                ah[mt][0] = ph[0];          ah[mt][1] = ph[8*CX_AP];
                ah[mt][2] = ph[4];          ah[mt][3] = ph[8*CX_AP + 4];
                al[mt][0] = pl[0];          al[mt][1] = pl[8*CX_AP];
                al[mt][2] = pl[4];          al[mt][3] = pl[8*CX_AP + 4];
            }
            #pragma unroll
            for (int nt = 0; nt < 4; nt++) {
                int nrow = wn * 32 + nt * 8 + gid;
                const uint32_t* pbh = BH + (kwb + ctid) * CX_BP + nrow;
                const uint32_t* pbl = BL + (kwb + ctid) * CX_BP + nrow;
                uint32_t bh_[2] = { pbh[0], pbh[4*CX_BP] };
                uint32_t bl_[2] = { pbl[0], pbl[4*CX_BP] };
                #pragma unroll
                for (int mt = 0; mt < 2; mt++)
                    MMA3(acc[mt][nt], ah[mt], al[mt], bh_, bl_);
            }
        }
    }

    #pragma unroll
    for (int mt = 0; mt < 2; mt++)
        #pragma unroll
        for (int nt = 0; nt < 4; nt++) {
            int row = m0 + wm * 32 + mt * 16 + gid;
            int col = wn * 32 + nt * 8 + 2 * ctid;
            float* op = g_ctx + ((size_t)b * SS + row) * EE + h * DD + col;
            *(float2*)op = make_float2(acc[mt][nt][0], acc[mt][nt][1]);
            *(float2*)(op + (size_t)8 * EE) = make_float2(acc[mt][nt][2], acc[mt][nt][3]);
        }
}

// =============================================================================
// Kernel 3: output projection, split-bf16 (round 7, unchanged).
// =============================================================================
#define GF_AP 20
#define GF_AHo 0
#define GF_ALo 2560
#define GF_BHo 5120
#define GF_BLo 6400
#define GF_SMEM_WORDS 7680
#define GF_SMEM_BYTES (GF_SMEM_WORDS * 4)

__global__ __launch_bounds__(256) void fc_mma_kernel(
    const float* __restrict__ fcw, const float* __restrict__ fcb,
    float* __restrict__ out)
{
    extern __shared__ uint32_t su[];
    uint32_t* AH = su + GF_AHo;
    uint32_t* AL = su + GF_ALo;
    uint32_t* BH = su + GF_BHo;
    uint32_t* BL = su + GF_BLo;

    const int b  = blockIdx.z;
    const int m0 = blockIdx.x * 128;
    const int n0 = blockIdx.y * 64;

    const float* ctx = g_ctx + (size_t)b * SS * EE;

    const int tid  = threadIdx.x;
    const int lane = tid & 31;
    const int w8   = tid >> 5;
    const int wm   = w8 >> 1;
    const int wn   = w8 & 1;
    const int gid  = lane >> 2;
    const int ctid = lane & 3;

    float acc[2][4][4];
    #pragma unroll
    for (int i = 0; i < 2; i++)
        #pragma unroll
        for (int j = 0; j < 4; j++)
            #pragma unroll
            for (int q = 0; q < 4; q++) acc[i][j][q] = 0.f;

    for (int kg = 0; kg < EE; kg += 32) {
        __syncthreads();
        #pragma unroll
        for (int p = 0; p < 2; p++) {
            int idx = tid + p * 256;
            int r   = idx >> 2;
            int kq  = (idx & 3) << 3;
            const float* ar = fcw + (size_t)(m0 + r) * EE + kg + kq;
            float4 a0 = *(const float4*)ar;
            float4 a1 = *(const float4*)(ar + 4);
            uint4 hv, lv;
            split2_bf16(a0.x, a0.y, hv.x, lv.x);
            split2_bf16(a0.z, a0.w, hv.y, lv.y);
            split2_bf16(a1.x, a1.y, hv.z, lv.z);
            split2_bf16(a1.z, a1.w, hv.w, lv.w);
            *(uint4*)(AH + r * GF_AP + (idx & 3) * 4) = hv;
            *(uint4*)(AL + r * GF_AP + (idx & 3) * 4) = lv;
        }
        {
            int r  = tid >> 2;
            int kq = (tid & 3) << 3;
            const float* br = ctx + (size_t)(n0 + r) * EE + kg + kq;
            float4 b0 = *(const float4*)br;
            float4 b1 = *(const float4*)(br + 4);
            uint4 hv, lv;
            split2_bf16(b0.x, b0.y, hv.x, lv.x);
            split2_bf16(b0.z, b0.w, hv.y, lv.y);
            split2_bf16(b1.x, b1.y, hv.z, lv.z);
            split2_bf16(b1.z, b1.w, hv.w, lv.w);
            *(uint4*)(BH + r * GF_AP + (tid & 3) * 4) = hv;
            *(uint4*)(BL + r * GF_AP + (tid & 3) * 4) = lv;
        }
        __syncthreads();

        #pragma unroll
        for (int kwb = 0; kwb < 16; kwb += 8) {
            uint32_t ah[2][4], al[2][4];
            #pragma unroll
            for (int mt = 0; mt < 2; mt++) {
                int mrow = wm * 32 + mt * 16 + gid;
                const uint32_t* ph = AH + mrow * GF_AP + kwb + ctid;
                const uint32_t* pl = AL + mrow * GF_AP + kwb + ctid;
                ah[mt][0] = ph[0];          ah[mt][1] = ph[8*GF_AP];
                ah[mt][2] = ph[4];          ah[mt][3] = ph[8*GF_AP + 4];
                al[mt][0] = pl[0];          al[mt][1] = pl[8*GF_AP];
                al[mt][2] = pl[4];          al[mt][3] = pl[8*GF_AP + 4];
            }
            #pragma unroll
            for (int nt = 0; nt < 4; nt++) {
                int nrow = wn * 32 + nt * 8 + gid;
                const uint32_t* pbh = BH + nrow * GF_AP + kwb + ctid;
                const uint32_t* pbl = BL + nrow * GF_AP + kwb + ctid;
                uint32_t bh_[2] = { pbh[0], pbh[4] };
                uint32_t bl_[2] = { pbl[0], pbl[4] };
                #pragma unroll
                for (int mt = 0; mt < 2; mt++)
                    MMA3(acc[mt][nt], ah[mt], al[mt], bh_, bl_);
            }
        }
    }

    #pragma unroll
    for (int mt = 0; mt < 2; mt++) {
        int row = m0 + wm * 32 + mt * 16 + gid;
        float fb0 = fcb[row];
        float fb1 = fcb[row + 8];
        #pragma unroll
        for (int nt = 0; nt < 4; nt++) {
            int col = n0 + wn * 32 + nt * 8 + 2 * ctid;
            *(float2*)(out + ((size_t)b * EE + row) * SS + col) =
                make_float2(acc[mt][nt][0] + fb0, acc[mt][nt][1] + fb0);
            *(float2*)(out + ((size_t)b * EE + row + 8) * SS + col) =
                make_float2(acc[mt][nt][2] + fb1, acc[mt][nt][3] + fb1);
        }
    }
}

// =============================================================================
extern "C" void kernel_launch(void* const* d_in, const int* in_sizes, int n_in,
                              void* d_out, int out_size)
{
    const float* q_img = (const float*)d_in[0];
    const float* k_img = (const float*)d_in[1];
    const float* v_img = (const float*)d_in[2];
    const float* wq_w  = (const float*)d_in[3];
    const float* wq_b  = (const float*)d_in[4];
    const float* wk_w  = (const float*)d_in[5];
    const float* wk_b  = (const float*)d_in[6];
    const float* wv_w  = (const float*)d_in[7];
    const float* wv_b  = (const float*)d_in[8];
    const float* fc_w  = (const float*)d_in[9];
    const float* fc_b  = (const float*)d_in[10];

    float* out   = (float*)d_out;
    float* probs = out + (size_t)BB * EE * SS;   // tuple output: (out, probs)

    cudaFuncSetAttribute(proj_mma_kernel, cudaFuncAttributeMaxDynamicSharedMemorySize,
                         GP_SMEM_BYTES);
    cudaFuncSetAttribute(scores_mma_kernel, cudaFuncAttributeMaxDynamicSharedMemorySize,
                         SK_SMEM_BYTES);
    cudaFuncSetAttribute(ctx_mma_kernel, cudaFuncAttributeMaxDynamicSharedMemorySize,
                         CX_SMEM_BYTES);
    cudaFuncSetAttribute(fc_mma_kernel, cudaFuncAttributeMaxDynamicSharedMemorySize,
                         GF_SMEM_BYTES);

    // 1) QKV projections
    proj_mma_kernel<<<dim3(SS / 128, EE / 64, 3 * BB), 256, GP_SMEM_BYTES>>>(
        q_img, k_img, v_img, wq_w, wk_w, wv_w, wq_b, wk_b, wv_b);

    // 2a) scores + exp + row partial sums (unnormalized P~ in probs)
    scores_mma_kernel<<<dim3(SS / 128, SS / 64, BB * NH), 256, SK_SMEM_BYTES>>>(probs);

    // 2c) ctx = P @ V with fused normalization + normalized probs write-back
    ctx_mma_kernel<<<dim3(SS / 128, 1, BB * NH), 256, CX_SMEM_BYTES>>>(probs);

    // 3) output projection
    fc_mma_kernel<<<dim3(EE / 128, SS / 64, BB), 256, GF_SMEM_BYTES>>>(fc_w, fc_b, out);
}

// round 9
// speedup vs baseline: 1.0201x; 1.0201x over previous
#include <cuda_runtime.h>
#include <cuda_bf16.h>
#include <cstdint>

// Problem dims
#define BB 8
#define SS 1024          // IMG*IMG
#define EE 768           // D_EMBED == D_MODEL
#define NH 12
#define DD 64

// ---------------- scratch (device globals; no allocs allowed) ----------------
__device__ float g_q[BB * SS * EE];
__device__ float g_k[BB * SS * EE];
__device__ float g_v[BB * SS * EE];
__device__ float g_ctx[BB * SS * EE];

// =============================================================================
// bf16 split helpers: x = hi + lo, both bf16. Word = k-pair (2j, 2j+1).
// Within each 8-kw block, words are stored PERMUTED: offset o(j)=2*(j&3)+(j>>2)
// so a fragment's (kw=ctid, kw=ctid+4) pair sits at consecutive words -> LDS.64.
// =============================================================================
__device__ __forceinline__ void split2_bf16(float x0, float x1,
                                            uint32_t& hw, uint32_t& lw) {
    __nv_bfloat162 h = __floats2bfloat162_rn(x0, x1);
    float2 hf = __bfloat1622float2(h);
    __nv_bfloat162 l = __floats2bfloat162_rn(x0 - hf.x, x1 - hf.y);
    hw = *reinterpret_cast<uint32_t*>(&h);
    lw = *reinterpret_cast<uint32_t*>(&l);
}

__device__ __forceinline__ void mma_bf16(float* d, const uint32_t* a, const uint32_t* b) {
    asm volatile(
        "mma.sync.aligned.m16n8k16.row.col.f32.bf16.bf16.f32 "
        "{%0,%1,%2,%3}, {%4,%5,%6,%7}, {%8,%9}, {%0,%1,%2,%3};"
        : "+f"(d[0]), "+f"(d[1]), "+f"(d[2]), "+f"(d[3])
        : "r"(a[0]), "r"(a[1]), "r"(a[2]), "r"(a[3]),
          "r"(b[0]), "r"(b[1]));
}

#define MMA3(accp, ah_, al_, bh_, bl_) \
    do { mma_bf16(accp, ah_, bh_); mma_bf16(accp, ah_, bl_); mma_bf16(accp, al_, bh_); } while (0)

#define U2(p) (*(const uint2*)(p))

// Pack helper for [row][kw]-layout staging: thread loads float4 at k and k+8,
// produces the 4 permuted-consecutive words [w(2t), w(2t+4), w(2t+1), w(2t+5)].
__device__ __forceinline__ void pack_rowkw(const float4& a0, const float4& a1,
                                           uint4& hv, uint4& lv) {
    split2_bf16(a0.x, a0.y, hv.x, lv.x);
    split2_bf16(a1.x, a1.y, hv.y, lv.y);
    split2_bf16(a0.z, a0.w, hv.z, lv.z);
    split2_bf16(a1.z, a1.w, hv.w, lv.w);
}

// =============================================================================
// Kernel 1: QKV projection. A = X^T (kw-major, m-interleaved), B = W [n][kw].
//   Y[s,o] = sum_c X[b][c][s] * W[o][c] + bias[o]
// A plane: [16 kw][128 m'] pitch 136; m' interleaves (m, m+8) within 16-tiles.
// B plane: [64 n][16 kw-permuted] pitch 24.
// =============================================================================
#define GP_AP 136
#define GP_BP 24
#define GP_AHo 0
#define GP_ALo 2176
#define GP_BHo 4352
#define GP_BLo 5888
#define GP_SMEM_WORDS 7424
#define GP_SMEM_BYTES (GP_SMEM_WORDS * 4)   // 29696

__global__ __launch_bounds__(256) void proj_mma_kernel(
    const float* __restrict__ xq, const float* __restrict__ xk, const float* __restrict__ xv,
    const float* __restrict__ wq, const float* __restrict__ wk, const float* __restrict__ wv,
    const float* __restrict__ bq, const float* __restrict__ bk, const float* __restrict__ bv)
{
    extern __shared__ uint32_t su[];
    uint32_t* AH = su + GP_AHo;
    uint32_t* AL = su + GP_ALo;
    uint32_t* BH = su + GP_BHo;
    uint32_t* BL = su + GP_BLo;

    const int mat = blockIdx.z >> 3;
    const int b   = blockIdx.z & 7;

    const float* x; const float* w; const float* bi; float* y;
    if (mat == 0)      { x = xq; w = wq; bi = bq; y = g_q; }
    else if (mat == 1) { x = xk; w = wk; bi = bk; y = g_k; }
    else               { x = xv; w = wv; bi = bv; y = g_v; }
    x += (size_t)b * EE * SS;
    y += (size_t)b * SS * EE;

    const int m0 = blockIdx.x * 128;
    const int n0 = blockIdx.y * 64;

    const int tid  = threadIdx.x;
    const int lane = tid & 31;
    const int w8   = tid >> 5;
    const int wm   = w8 >> 1;
    const int wn   = w8 & 1;
    const int gid  = lane >> 2;
    const int ctid = lane & 3;

    float acc[2][4][4];
    #pragma unroll
    for (int i = 0; i < 2; i++)
        #pragma unroll
        for (int j = 0; j < 4; j++)
            #pragma unroll
            for (int q = 0; q < 4; q++) acc[i][j][q] = 0.f;

    for (int kg = 0; kg < EE; kg += 32) {
        __syncthreads();
        // stage A: X rows [kg..kg+32) -> At[kw][m'], m' = (lm&7)*2 + (lm>>3)
        #pragma unroll
        for (int p = 0; p < 2; p++) {
            int idx  = tid + p * 256;        // 0..511
            int j    = idx >> 5;             // kw 0..15
            int q    = idx & 31;
            int tile = q >> 2;               // 16-m tile 0..7
            int t    = q & 3;
            const float* xr = x + (size_t)(kg + 2 * j) * SS + m0 + tile * 16 + 2 * t;
            float2 x00 = *(const float2*)xr;
            float2 x01 = *(const float2*)(xr + 8);
            float2 x10 = *(const float2*)(xr + SS);
            float2 x11 = *(const float2*)(xr + SS + 8);
            uint4 hv, lv;
            split2_bf16(x00.x, x10.x, hv.x, lv.x);   // m' 4t+0  (m = 2t)
            split2_bf16(x01.x, x11.x, hv.y, lv.y);   // m' 4t+1  (m = 2t+8)
            split2_bf16(x00.y, x10.y, hv.z, lv.z);   // m' 4t+2  (m = 2t+1)
            split2_bf16(x01.y, x11.y, hv.w, lv.w);   // m' 4t+3  (m = 2t+9)
            *(uint4*)(AH + j * GP_AP + tile * 16 + 4 * t) = hv;
            *(uint4*)(AL + j * GP_AP + tile * 16 + 4 * t) = lv;
        }
        // stage B: W rows [n0..n0+64) x 32 k -> Bs[n][kw-permuted]
        {
            int r   = tid >> 2;              // 0..63
            int i   = tid & 3;
            int blk = i >> 1;
            int t   = i & 1;
            const float* wr = w + (size_t)(n0 + r) * EE + kg + blk * 16 + t * 4;
            float4 b0 = *(const float4*)wr;
            float4 b1 = *(const float4*)(wr + 8);
            uint4 hv, lv;
            pack_rowkw(b0, b1, hv, lv);
            *(uint4*)(BH + r * GP_BP + blk * 8 + t * 4) = hv;
            *(uint4*)(BL + r * GP_BP + blk * 8 + t * 4) = lv;
        }
        __syncthreads();

        #pragma unroll
        for (int kwb = 0; kwb < 16; kwb += 8) {
            uint32_t ah[2][4], al[2][4];
            #pragma unroll
            for (int mt = 0; mt < 2; mt++) {
                int tb = (wm * 2 + mt) * 16 + 2 * gid;
                uint2 u0h = U2(AH + (kwb + ctid) * GP_AP + tb);
                uint2 u1h = U2(AH + (kwb + ctid + 4) * GP_AP + tb);
                uint2 u0l = U2(AL + (kwb + ctid) * GP_AP + tb);
                uint2 u1l = U2(AL + (kwb + ctid + 4) * GP_AP + tb);
                ah[mt][0] = u0h.x; ah[mt][1] = u0h.y; ah[mt][2] = u1h.x; ah[mt][3] = u1h.y;
                al[mt][0] = u0l.x; al[mt][1] = u0l.y; al[mt][2] = u1l.x; al[mt][3] = u1l.y;
            }
            #pragma unroll
            for (int nt = 0; nt < 4; nt++) {
                int nrow = wn * 32 + nt * 8 + gid;
                uint2 uh = U2(BH + nrow * GP_BP + kwb + 2 * ctid);
                uint2 ul = U2(BL + nrow * GP_BP + kwb + 2 * ctid);
                uint32_t bh_[2] = { uh.x, uh.y };
                uint32_t bl_[2] = { ul.x, ul.y };
                #pragma unroll
                for (int mt = 0; mt < 2; mt++)
                    MMA3(acc[mt][nt], ah[mt], al[mt], bh_, bl_);
            }
        }
    }

    #pragma unroll
    for (int nt = 0; nt < 4; nt++) {
        int col = n0 + wn * 32 + nt * 8 + 2 * ctid;
        float b0 = bi[col], b1 = bi[col + 1];
        #pragma unroll
        for (int mt = 0; mt < 2; mt++) {
            int row = m0 + wm * 32 + mt * 16 + gid;
            *(float2*)(y + (size_t)row * EE + col) =
                make_float2(acc[mt][nt][0] + b0, acc[mt][nt][1] + b1);
            *(float2*)(y + (size_t)(row + 8) * EE + col) =
                make_float2(acc[mt][nt][2] + b0, acc[mt][nt][3] + b1);
        }
    }
}

// =============================================================================
// Kernel 2a: scores GEMM. A=Q[m][kw], B=K[n][kw], both permuted, pitch 40.
// K=64 staged once (32 kw words). Raw scaled scores -> probs.
// =============================================================================
#define SK_P 40
#define SK_AHo 0
#define SK_ALo 5120
#define SK_BHo 10240
#define SK_BLo 12800
#define SK_SMEM_WORDS 15360
#define SK_SMEM_BYTES (SK_SMEM_WORDS * 4)   // 61440

__global__ __launch_bounds__(256) void scores_mma_kernel(float* __restrict__ probs)
{
    extern __shared__ uint32_t su[];
    uint32_t* AH = su + SK_AHo;
    uint32_t* AL = su + SK_ALo;
    uint32_t* BH = su + SK_BHo;
    uint32_t* BL = su + SK_BLo;

    const int bh = blockIdx.z;
    const int b  = bh / NH;
    const int h  = bh % NH;
    const int m0 = blockIdx.x * 128;
    const int n0 = blockIdx.y * 64;

    const float* qp = g_q + ((size_t)b * SS) * EE + h * DD;
    const float* kp = g_k + ((size_t)b * SS) * EE + h * DD;

    const int tid  = threadIdx.x;
    const int lane = tid & 31;
    const int w8   = tid >> 5;
    const int wm   = w8 >> 1;
    const int wn   = w8 & 1;
    const int gid  = lane >> 2;
    const int ctid = lane & 3;

    // stage A (Q): 128 rows x 64 k
    #pragma unroll
    for (int p = 0; p < 4; p++) {
        int idx = tid + p * 256;             // 0..1023
        int r   = idx >> 3;
        int i   = idx & 7;
        int blk = i >> 1;
        int t   = i & 1;
        const float* qr = qp + (size_t)(m0 + r) * EE + blk * 16 + t * 4;
        float4 a0 = *(const float4*)qr;
        float4 a1 = *(const float4*)(qr + 8);
        uint4 hv, lv;
        pack_rowkw(a0, a1, hv, lv);
        *(uint4*)(AH + r * SK_P + blk * 8 + t * 4) = hv;
        *(uint4*)(AL + r * SK_P + blk * 8 + t * 4) = lv;
    }
    // stage B (K): 64 rows x 64 k
    #pragma unroll
    for (int p = 0; p < 2; p++) {
        int idx = tid + p * 256;             // 0..511
        int r   = idx >> 3;
        int i   = idx & 7;
        int blk = i >> 1;
        int t   = i & 1;
        const float* kr = kp + (size_t)(n0 + r) * EE + blk * 16 + t * 4;
        float4 b0 = *(const float4*)kr;
        float4 b1 = *(const float4*)(kr + 8);
        uint4 hv, lv;
        pack_rowkw(b0, b1, hv, lv);
        *(uint4*)(BH + r * SK_P + blk * 8 + t * 4) = hv;
        *(uint4*)(BL + r * SK_P + blk * 8 + t * 4) = lv;
    }
    __syncthreads();

    float acc[2][4][4];
    #pragma unroll
    for (int i = 0; i < 2; i++)
        #pragma unroll
        for (int j = 0; j < 4; j++)
            #pragma unroll
            for (int q = 0; q < 4; q++) acc[i][j][q] = 0.f;

    #pragma unroll
    for (int kwb = 0; kwb < 32; kwb += 8) {
        uint32_t ah[2][4], al[2][4];
        #pragma unroll
        for (int mt = 0; mt < 2; mt++) {
            int mrow = wm * 32 + mt * 16 + gid;
            uint2 u0h = U2(AH + mrow * SK_P + kwb + 2 * ctid);
            uint2 u1h = U2(AH + (mrow + 8) * SK_P + kwb + 2 * ctid);
            uint2 u0l = U2(AL + mrow * SK_P + kwb + 2 * ctid);
            uint2 u1l = U2(AL + (mrow + 8) * SK_P + kwb + 2 * ctid);
            ah[mt][0] = u0h.x; ah[mt][1] = u1h.x; ah[mt][2] = u0h.y; ah[mt][3] = u1h.y;
            al[mt][0] = u0l.x; al[mt][1] = u1l.x; al[mt][2] = u0l.y; al[mt][3] = u1l.y;
        }
        #pragma unroll
        for (int nt = 0; nt < 4; nt++) {
            int nrow = wn * 32 + nt * 8 + gid;
            uint2 uh = U2(BH + nrow * SK_P + kwb + 2 * ctid);
            uint2 ul = U2(BL + nrow * SK_P + kwb + 2 * ctid);
            uint32_t bh_[2] = { uh.x, uh.y };
            uint32_t bl_[2] = { ul.x, ul.y };
            #pragma unroll
            for (int mt = 0; mt < 2; mt++)
                MMA3(acc[mt][nt], ah[mt], al[mt], bh_, bl_);
        }
    }

    float* pbase = probs + (size_t)bh * SS * SS;
    #pragma unroll
    for (int mt = 0; mt < 2; mt++)
        #pragma unroll
        for (int nt = 0; nt < 4; nt++) {
            int row = m0 + wm * 32 + mt * 16 + gid;
            int col = n0 + wn * 32 + nt * 8 + 2 * ctid;
            *(float2*)(pbase + (size_t)row * SS + col) =
                make_float2(acc[mt][nt][0] * 0.125f, acc[mt][nt][1] * 0.125f);
            *(float2*)(pbase + (size_t)(row + 8) * SS + col) =
                make_float2(acc[mt][nt][2] * 0.125f, acc[mt][nt][3] * 0.125f);
        }
}

// =============================================================================
// Kernel 2b: in-place row softmax (round 7, unchanged; HBM-bound at roof).
// =============================================================================
__global__ __launch_bounds__(256) void softmax_kernel(float* __restrict__ probs)
{
    const int warp = threadIdx.x >> 5;
    const int lane = threadIdx.x & 31;
    const size_t row = (size_t)blockIdx.x * 8 + warp;

    float4* rp = (float4*)(probs + row * SS);

    float4 v[8];
    #pragma unroll
    for (int i = 0; i < 8; i++) v[i] = rp[lane + 32 * i];

    float mx = -3.4e38f;
    #pragma unroll
    for (int i = 0; i < 8; i++)
        mx = fmaxf(mx, fmaxf(fmaxf(v[i].x, v[i].y), fmaxf(v[i].z, v[i].w)));
    #pragma unroll
    for (int o = 16; o > 0; o >>= 1)
        mx = fmaxf(mx, __shfl_xor_sync(0xFFFFFFFFu, mx, o));

    float sum = 0.f;
    #pragma unroll
    for (int i = 0; i < 8; i++) {
        v[i].x = __expf(v[i].x - mx);
        v[i].y = __expf(v[i].y - mx);
        v[i].z = __expf(v[i].z - mx);
        v[i].w = __expf(v[i].w - mx);
        sum += v[i].x + v[i].y + v[i].z + v[i].w;
    }
    #pragma unroll
    for (int o = 16; o > 0; o >>= 1)
        sum += __shfl_xor_sync(0xFFFFFFFFu, sum, o);

    float inv = 1.f / sum;
    #pragma unroll
    for (int i = 0; i < 8; i++) {
        v[i].x *= inv; v[i].y *= inv; v[i].z *= inv; v[i].w *= inv;
        rp[lane + 32 * i] = v[i];
    }
}

// =============================================================================
// Kernel 2c: ctx GEMM. A = P[m][kw] pitch 24; B = V kw-row-interleaved:
//   word (jl, n) of kwb-block blk at  blk*544 + (jl&3)*136 + 2n + (jl>>2)
// so the (jl=ctid, ctid+4) fragment pair is one LDS.64.
// =============================================================================
#define CX_AP 24
#define CX_BR 136          // per jl-row pitch inside a block
#define CX_BBLK 544        // 4 * 136
#define CX_AHo 0
#define CX_ALo 3072
#define CX_BHo 6144
#define CX_BLo 7232
#define CX_SMEM_WORDS 8320
#define CX_SMEM_BYTES (CX_SMEM_WORDS * 4)   // 33280

__global__ __launch_bounds__(256) void ctx_mma_kernel(const float* __restrict__ probs)
{
    extern __shared__ uint32_t su[];
    uint32_t* AH = su + CX_AHo;
    uint32_t* AL = su + CX_ALo;
    uint32_t* BH = su + CX_BHo;
    uint32_t* BL = su + CX_BLo;

    const int bh = blockIdx.z;
    const int b  = bh / NH;
    const int h  = bh % NH;
    const int m0 = blockIdx.x * 128;

    const float* pb = probs + (size_t)bh * SS * SS;
    const float* vb = g_v + ((size_t)b * SS) * EE + h * DD;

    const int tid  = threadIdx.x;
    const int lane = tid & 31;
    const int w8   = tid >> 5;
    const int wm   = w8 >> 1;
    const int wn   = w8 & 1;
    const int gid  = lane >> 2;
    const int ctid = lane & 3;

    float acc[2][4][4];
    #pragma unroll
    for (int i = 0; i < 2; i++)
        #pragma unroll
        for (int j = 0; j < 4; j++)
            #pragma unroll
            for (int q = 0; q < 4; q++) acc[i][j][q] = 0.f;

    for (int kg = 0; kg < SS; kg += 32) {
        __syncthreads();
        // stage A (P): 128 rows x 32 k -> [m][kw-permuted] pitch 24
        #pragma unroll
        for (int p = 0; p < 2; p++) {
            int idx = tid + p * 256;         // 0..511
            int r   = idx >> 2;
            int i   = idx & 3;
            int blk = i >> 1;
            int t   = i & 1;
            const float* pr = pb + (size_t)(m0 + r) * SS + kg + blk * 16 + t * 4;
            float4 a0 = *(const float4*)pr;
            float4 a1 = *(const float4*)(pr + 8);
            uint4 hv, lv;
            pack_rowkw(a0, a1, hv, lv);
            *(uint4*)(AH + r * CX_AP + blk * 8 + t * 4) = hv;
            *(uint4*)(AL + r * CX_AP + blk * 8 + t * 4) = lv;
        }
        // stage B (V): 32 k-rows x 64 d -> kw-row-interleaved blocks
        {
            int blk = tid >> 7;              // 0..1
            int jj  = (tid >> 5) & 3;        // 0..3
            int n0  = (tid & 31) * 2;        // 0..62
            int kbase = kg + blk * 16;
            const float* vr = vb + (size_t)(kbase + 2 * jj) * EE + n0;
            float2 r0 = *(const float2*)vr;
            float2 r1 = *(const float2*)(vr + EE);
            float2 r2 = *(const float2*)(vr + 8 * EE);
            float2 r3 = *(const float2*)(vr + 9 * EE);
            uint4 hv, lv;
            split2_bf16(r0.x, r1.x, hv.x, lv.x);   // w(jj,   n0)
            split2_bf16(r2.x, r3.x, hv.y, lv.y);   // w(jj+4, n0)
            split2_bf16(r0.y, r1.y, hv.z, lv.z);   // w(jj,   n0+1)
            split2_bf16(r2.y, r3.y, hv.w, lv.w);   // w(jj+4, n0+1)
            *(uint4*)(BH + blk * CX_BBLK + jj * CX_BR + 2 * n0) = hv;
            *(uint4*)(BL + blk * CX_BBLK + jj * CX_BR + 2 * n0) = lv;
        }
        __syncthreads();

        #pragma unroll
        for (int kwb = 0; kwb < 16; kwb += 8) {
            uint32_t ah[2][4], al[2][4];
            #pragma unroll
            for (int mt = 0; mt < 2; mt++) {
                int mrow = wm * 32 + mt * 16 + gid;
                uint2 u0h = U2(AH + mrow * CX_AP + kwb + 2 * ctid);
                uint2 u1h = U2(AH + (mrow + 8) * CX_AP + kwb + 2 * ctid);
                uint2 u0l = U2(AL + mrow * CX_AP + kwb + 2 * ctid);
                uint2 u1l = U2(AL + (mrow + 8) * CX_AP + kwb + 2 * ctid);
                ah[mt][0] = u0h.x; ah[mt][1] = u1h.x; ah[mt][2] = u0h.y; ah[mt][3] = u1h.y;
                al[mt][0] = u0l.x; al[mt][1] = u1l.x; al[mt][2] = u0l.y; al[mt][3] = u1l.y;
            }
            const uint32_t* bbh = BH + (kwb >> 3) * CX_BBLK + ctid * CX_BR;
            const uint32_t* bbl = BL + (kwb >> 3) * CX_BBLK + ctid * CX_BR;
            #pragma unroll
            for (int nt = 0; nt < 4; nt++) {
                int nrow = wn * 32 + nt * 8 + gid;
                uint2 uh = U2(bbh + 2 * nrow);
                uint2 ul = U2(bbl + 2 * nrow);
                uint32_t bh_[2] = { uh.x, uh.y };
                uint32_t bl_[2] = { ul.x, ul.y };
                #pragma unroll
                for (int mt = 0; mt < 2; mt++)
                    MMA3(acc[mt][nt], ah[mt], al[mt], bh_, bl_);
            }
        }
    }

    #pragma unroll
    for (int mt = 0; mt < 2; mt++)
        #pragma unroll
        for (int nt = 0; nt < 4; nt++) {
            int row = m0 + wm * 32 + mt * 16 + gid;
            int col = wn * 32 + nt * 8 + 2 * ctid;
            float* op = g_ctx + ((size_t)b * SS + row) * EE + h * DD + col;
            *(float2*)op = make_float2(acc[mt][nt][0], acc[mt][nt][1]);
            *(float2*)(op + (size_t)8 * EE) = make_float2(acc[mt][nt][2], acc[mt][nt][3]);
        }
}

// =============================================================================
// Kernel 3: output projection. A = fc_w[m][kw], B = ctx[n][kw], pitch 24.
// =============================================================================
#define GF_AP 24
#define GF_AHo 0
#define GF_ALo 3072
#define GF_BHo 6144
#define GF_BLo 7680
#define GF_SMEM_WORDS 9216
#define GF_SMEM_BYTES (GF_SMEM_WORDS * 4)   // 36864

__global__ __launch_bounds__(256) void fc_mma_kernel(
    const float* __restrict__ fcw, const float* __restrict__ fcb,
    float* __restrict__ out)
{
    extern __shared__ uint32_t su[];
    uint32_t* AH = su + GF_AHo;
    uint32_t* AL = su + GF_ALo;
    uint32_t* BH = su + GF_BHo;
    uint32_t* BL = su + GF_BLo;

    const int b  = blockIdx.z;
    const int m0 = blockIdx.x * 128;
    const int n0 = blockIdx.y * 64;

    const float* ctx = g_ctx + (size_t)b * SS * EE;

    const int tid  = threadIdx.x;
    const int lane = tid & 31;
    const int w8   = tid >> 5;
    const int wm   = w8 >> 1;
    const int wn   = w8 & 1;
    const int gid  = lane >> 2;
    const int ctid = lane & 3;

    float acc[2][4][4];
    #pragma unroll
    for (int i = 0; i < 2; i++)
        #pragma unroll
        for (int j = 0; j < 4; j++)
            #pragma unroll
            for (int q = 0; q < 4; q++) acc[i][j][q] = 0.f;

    for (int kg = 0; kg < EE; kg += 32) {
        __syncthreads();
        // stage A (fc_w): 128 rows x 32 k
        #pragma unroll
        for (int p = 0; p < 2; p++) {
            int idx = tid + p * 256;
            int r   = idx >> 2;
            int i   = idx & 3;
            int blk = i >> 1;
            int t   = i & 1;
            const float* ar = fcw + (size_t)(m0 + r) * EE + kg + blk * 16 + t * 4;
            float4 a0 = *(const float4*)ar;
            float4 a1 = *(const float4*)(ar + 8);
            uint4 hv, lv;
            pack_rowkw(a0, a1, hv, lv);
            *(uint4*)(AH + r * GF_AP + blk * 8 + t * 4) = hv;
            *(uint4*)(AL + r * GF_AP + blk * 8 + t * 4) = lv;
        }
        // stage B (ctx): 64 rows x 32 k
        {
            int r   = tid >> 2;
            int i   = tid & 3;
            int blk = i >> 1;
            int t   = i & 1;
            const float* br = ctx + (size_t)(n0 + r) * EE + kg + blk * 16 + t * 4;
            float4 b0 = *(const float4*)br;
            float4 b1 = *(const float4*)(br + 8);
            uint4 hv, lv;
            pack_rowkw(b0, b1, hv, lv);
            *(uint4*)(BH + r * GF_AP + blk * 8 + t * 4) = hv;
            *(uint4*)(BL + r * GF_AP + blk * 8 + t * 4) = lv;
        }
        __syncthreads();

        #pragma unroll
        for (int kwb = 0; kwb < 16; kwb += 8) {
            uint32_t ah[2][4], al[2][4];
            #pragma unroll
            for (int mt = 0; mt < 2; mt++) {
                int mrow = wm * 32 + mt * 16 + gid;
                uint2 u0h = U2(AH + mrow * GF_AP + kwb + 2 * ctid);
                uint2 u1h = U2(AH + (mrow + 8) * GF_AP + kwb + 2 * ctid);
                uint2 u0l = U2(AL + mrow * GF_AP + kwb + 2 * ctid);
                uint2 u1l = U2(AL + (mrow + 8) * GF_AP + kwb + 2 * ctid);
                ah[mt][0] = u0h.x; ah[mt][1] = u1h.x; ah[mt][2] = u0h.y; ah[mt][3] = u1h.y;
                al[mt][0] = u0l.x; al[mt][1] = u1l.x; al[mt][2] = u0l.y; al[mt][3] = u1l.y;
            }
            #pragma unroll
            for (int nt = 0; nt < 4; nt++) {
                int nrow = wn * 32 + nt * 8 + gid;
                uint2 uh = U2(BH + nrow * GF_AP + kwb + 2 * ctid);
                uint2 ul = U2(BL + nrow * GF_AP + kwb + 2 * ctid);
                uint32_t bh_[2] = { uh.x, uh.y };
                uint32_t bl_[2] = { ul.x, ul.y };
                #pragma unroll
                for (int mt = 0; mt < 2; mt++)
                    MMA3(acc[mt][nt], ah[mt], al[mt], bh_, bl_);
            }
        }
    }

    #pragma unroll
    for (int mt = 0; mt < 2; mt++) {
        int row = m0 + wm * 32 + mt * 16 + gid;
        float fb0 = fcb[row];
        float fb1 = fcb[row + 8];
        #pragma unroll
        for (int nt = 0; nt < 4; nt++) {
            int col = n0 + wn * 32 + nt * 8 + 2 * ctid;
            *(float2*)(out + ((size_t)b * EE + row) * SS + col) =
                make_float2(acc[mt][nt][0] + fb0, acc[mt][nt][1] + fb0);
            *(float2*)(out + ((size_t)b * EE + row + 8) * SS + col) =
                make_float2(acc[mt][nt][2] + fb1, acc[mt][nt][3] + fb1);
        }
    }
}

// =============================================================================
extern "C" void kernel_launch(void* const* d_in, const int* in_sizes, int n_in,
                              void* d_out, int out_size)
{
    const float* q_img = (const float*)d_in[0];
    const float* k_img = (const float*)d_in[1];
    const float* v_img = (const float*)d_in[2];
    const float* wq_w  = (const float*)d_in[3];
    const float* wq_b  = (const float*)d_in[4];
    const float* wk_w  = (const float*)d_in[5];
    const float* wk_b  = (const float*)d_in[6];
    const float* wv_w  = (const float*)d_in[7];
    const float* wv_b  = (const float*)d_in[8];
    const float* fc_w  = (const float*)d_in[9];
    const float* fc_b  = (const float*)d_in[10];

    float* out   = (float*)d_out;
    float* probs = out + (size_t)BB * EE * SS;   // tuple output: (out, probs)

    cudaFuncSetAttribute(proj_mma_kernel, cudaFuncAttributeMaxDynamicSharedMemorySize,
                         GP_SMEM_BYTES);
    cudaFuncSetAttribute(scores_mma_kernel, cudaFuncAttributeMaxDynamicSharedMemorySize,
                         SK_SMEM_BYTES);
    cudaFuncSetAttribute(ctx_mma_kernel, cudaFuncAttributeMaxDynamicSharedMemorySize,
                         CX_SMEM_BYTES);
    cudaFuncSetAttribute(fc_mma_kernel, cudaFuncAttributeMaxDynamicSharedMemorySize,
                         GF_SMEM_BYTES);

    // 1) QKV projections
    proj_mma_kernel<<<dim3(SS / 128, EE / 64, 3 * BB), 256, GP_SMEM_BYTES>>>(
        q_img, k_img, v_img, wq_w, wk_w, wv_w, wq_b, wk_b, wv_b);

    // 2a) scores -> raw into probs buffer
    scores_mma_kernel<<<dim3(SS / 128, SS / 64, BB * NH), 256, SK_SMEM_BYTES>>>(probs);

    // 2b) in-place softmax over probs rows
    softmax_kernel<<<(BB * NH * SS) / 8, 256>>>(probs);

    // 2c) ctx = P @ V
    ctx_mma_kernel<<<dim3(SS / 128, 1, BB * NH), 256, CX_SMEM_BYTES>>>(probs);

    // 3) output projection
    fc_mma_kernel<<<dim3(EE / 128, SS / 64, BB), 256, GF_SMEM_BYTES>>>(fc_w, fc_b, out);
}